// round 9
// baseline (speedup 1.0000x reference)
#include <cuda_runtime.h>
#include <cuda_fp16.h>
#include <math.h>
#include <stdint.h>

#define T_TOK 4096
#define HDIM  1024
#define IDIM  1408
#define NEXP  8
#define NPAIR (T_TOK * 2)
#define N2I   (2 * IDIM)           // 2816 (interleaved gate/up rows)
#define BM 128
#define BN 128
#define BKH 64                     // K halves per stage (128B rows)
#define MAXT 72

// smem: rows 128B data + 16B pad = 144B (ldmatrix stride 36 words -> conflict-free)
#define ROWB 144
#define REG  (128 * ROWB)          // 18432 B per operand region
#define O_AH 0
#define O_BH (REG)
#define O_BL (2 * REG)
#define STAGEB (3 * REG)           // 55296
#define SMEM_TOTAL (2 * STAGEB)    // 110592 -> 2 CTAs/SM

// ---------------- scratch (static device globals; no allocations) ----------
__device__ int   g_count[NEXP];
__device__ int   g_list [NEXP * T_TOK];
__device__ float g_wt   [NEXP * T_TOK];
__device__ int   g_base [NEXP];
__device__ int   g_tileE[MAXT];
__device__ int   g_tileRow[MAXT];
__device__ int   g_numTiles;

__device__ __half g_xh [(size_t)NPAIR * HDIM];
__device__ __half g_w1h[(size_t)NEXP * N2I * HDIM];   // interleaved: row 2i=gate_i, 2i+1=up_i
__device__ __half g_w1l[(size_t)NEXP * N2I * HDIM];
__device__ __half g_wdh[(size_t)NEXP * HDIM * IDIM];
__device__ __half g_wdl[(size_t)NEXP * HDIM * IDIM];
__device__ __half g_hh [(size_t)NPAIR * IDIM];

// ---------------- helpers -------------------------------------------------
__device__ __forceinline__ uint32_t smem_u32(const void* p) {
    uint32_t a;
    asm("{ .reg .u64 t; cvta.to.shared.u64 t, %1; cvt.u32.u64 %0, t; }" : "=r"(a) : "l"(p));
    return a;
}
__device__ __forceinline__ void cp16(uint32_t s, const void* g, bool v) {
    int sz = v ? 16 : 0;
    asm volatile("cp.async.cg.shared.global [%0], [%1], 16, %2;" :: "r"(s), "l"(g), "r"(sz) : "memory");
}
__device__ __forceinline__ void ldsm4(uint32_t* r, uint32_t addr) {
    asm volatile("ldmatrix.sync.aligned.m8n8.x4.shared.b16 {%0,%1,%2,%3}, [%4];"
                 : "=r"(r[0]), "=r"(r[1]), "=r"(r[2]), "=r"(r[3]) : "r"(addr));
}
__device__ __forceinline__ void mma16816(float* c, const uint32_t* a, uint32_t b0, uint32_t b1) {
    asm volatile("mma.sync.aligned.m16n8k16.row.col.f32.f16.f16.f32 "
                 "{%0,%1,%2,%3}, {%4,%5,%6,%7}, {%8,%9}, {%0,%1,%2,%3};"
                 : "+f"(c[0]), "+f"(c[1]), "+f"(c[2]), "+f"(c[3])
                 : "r"(a[0]), "r"(a[1]), "r"(a[2]), "r"(a[3]), "r"(b0), "r"(b1));
}
__device__ __forceinline__ void split_store(float4 v, __half* hp, __half* lp) {
    __half h0 = __float2half_rn(v.x), h1 = __float2half_rn(v.y);
    __half h2 = __float2half_rn(v.z), h3 = __float2half_rn(v.w);
    __half l0 = __float2half_rn(v.x - __half2float(h0));
    __half l1 = __float2half_rn(v.y - __half2float(h1));
    __half l2 = __float2half_rn(v.z - __half2float(h2));
    __half l3 = __float2half_rn(v.w - __half2float(h3));
    ((__half2*)hp)[0] = __halves2half2(h0, h1);
    ((__half2*)hp)[1] = __halves2half2(h2, h3);
    ((__half2*)lp)[0] = __halves2half2(l0, l1);
    ((__half2*)lp)[1] = __halves2half2(l2, l3);
}

// ---------------- init ----------------------------------------------------
__global__ void k_init() {
    if (threadIdx.x < NEXP) g_count[threadIdx.x] = 0;
}

// ---------------- zero output (atomic-accumulate base) --------------------
__global__ void k_zero(float* __restrict__ out) {
    size_t idx = (size_t)blockIdx.x * blockDim.x + threadIdx.x;
    if (idx < (size_t)T_TOK * HDIM / 4)
        *(float4*)(out + idx * 4) = make_float4(0.f, 0.f, 0.f, 0.f);
}

// ---------------- router: one warp per token ------------------------------
__global__ void k_router(const float* __restrict__ x, const float* __restrict__ rw) {
    int warp = (blockIdx.x * blockDim.x + threadIdx.x) >> 5;
    int lane = threadIdx.x & 31;
    if (warp >= T_TOK) return;
    const float* xr = x + (size_t)warp * HDIM;

    float xv[32];
#pragma unroll
    for (int j = 0; j < 32; j++) xv[j] = xr[lane + j * 32];

    float logits[NEXP];
#pragma unroll
    for (int e = 0; e < NEXP; e++) {
        const float* wr = rw + (size_t)e * HDIM;
        float acc = 0.f;
#pragma unroll
        for (int j = 0; j < 32; j++) acc += xv[j] * wr[lane + j * 32];
#pragma unroll
        for (int s = 16; s > 0; s >>= 1) acc += __shfl_xor_sync(0xffffffffu, acc, s);
        logits[e] = acc;
    }

    if (lane == 0) {
        int e1 = 0;
#pragma unroll
        for (int e = 1; e < NEXP; e++) if (logits[e] > logits[e1]) e1 = e;
        int e2 = (e1 == 0) ? 1 : 0;
#pragma unroll
        for (int e = 0; e < NEXP; e++)
            if (e != e1 && logits[e] > logits[e2]) e2 = e;
        float t  = expf(logits[e2] - logits[e1]);
        float w1 = 1.f / (1.f + t);
        float w2 = t   / (1.f + t);

        int i1 = atomicAdd(&g_count[e1], 1);
        g_list[e1 * T_TOK + i1] = warp;
        g_wt  [e1 * T_TOK + i1] = w1;

        int i2 = atomicAdd(&g_count[e2], 1);
        g_list[e2 * T_TOK + i2] = warp;
        g_wt  [e2 * T_TOK + i2] = w2;
    }
}

// ---------------- tile table ---------------------------------------------
__global__ void k_build() {
    if (threadIdx.x != 0 || blockIdx.x != 0) return;
    int base = 0, nt = 0;
    for (int e = 0; e < NEXP; e++) {
        g_base[e] = base;
        int c = g_count[e];
        int tiles = (c + BM - 1) / BM;
        for (int r = 0; r < tiles; r++) {
            g_tileE[nt]   = e;
            g_tileRow[nt] = r * BM;
            nt++;
        }
        base += c;
    }
    g_numTiles = nt;
}

// ---------------- weight split: fp32 -> (hi,lo), interleave gate/up -------
__global__ void k_splitw(const float* __restrict__ wg, const float* __restrict__ wu,
                         const float* __restrict__ wd) {
    const size_t WG = (size_t)NEXP * IDIM * HDIM;
    const size_t WD = (size_t)NEXP * HDIM * IDIM;
    size_t idx4 = (size_t)blockIdx.x * blockDim.x + threadIdx.x;
    size_t f = idx4 * 4;
    if (f < WG) {                       // gate -> row 2i
        size_t e = f / ((size_t)IDIM * HDIM);
        size_t r = f % ((size_t)IDIM * HDIM);
        size_t i = r / HDIM, k = r % HDIM;
        float4 v = *(const float4*)(wg + f);
        size_t dst = ((size_t)e * N2I + 2 * i) * HDIM + k;
        split_store(v, g_w1h + dst, g_w1l + dst);
    } else if (f < 2 * WG) {            // up -> row 2i+1
        size_t f2 = f - WG;
        size_t e = f2 / ((size_t)IDIM * HDIM);
        size_t r = f2 % ((size_t)IDIM * HDIM);
        size_t i = r / HDIM, k = r % HDIM;
        float4 v = *(const float4*)(wu + f2);
        size_t dst = ((size_t)e * N2I + 2 * i + 1) * HDIM + k;
        split_store(v, g_w1h + dst, g_w1l + dst);
    } else if (f < 2 * WG + WD) {       // down, linear
        size_t f2 = f - 2 * WG;
        float4 v = *(const float4*)(wd + f2);
        split_store(v, g_wdh + f2, g_wdl + f2);
    }
}

// ---------------- gather: fp32 rows -> fp16 hi, sorted order --------------
__global__ void k_gather(const float* __restrict__ x) {
    int p = blockIdx.x;
    int e = 0;
#pragma unroll
    for (int i = 0; i < NEXP; i++)
        if (p >= g_base[i] && p < g_base[i] + g_count[i]) e = i;
    int r   = p - g_base[e];
    int tok = g_list[e * T_TOK + r];
    const float* src = x + (size_t)tok * HDIM;
    __half* dst = g_xh + (size_t)p * HDIM;
    for (int c = threadIdx.x * 4; c < HDIM; c += blockDim.x * 4) {
        float4 v = *(const float4*)(src + c);
        ((__half2*)(dst + c))[0] = __halves2half2(__float2half_rn(v.x), __float2half_rn(v.y));
        ((__half2*)(dst + c))[1] = __halves2half2(__float2half_rn(v.z), __float2half_rn(v.w));
    }
}

// ---------------- 2-term split HMMA GEMM, pipelined fragments --------------
// C = Ah @ (Bh + Bl)^T ; G1 fuses silu(gate)*up -> g_hh ; G2 atomically adds to out
template <int KD, bool G2>
__global__ void __launch_bounds__(256, 2) k_gemm(float* __restrict__ out) {
    int tileIdx = blockIdx.y;
    if (tileIdx >= g_numTiles) return;
    extern __shared__ char smem[];
    uint32_t sb = smem_u32(smem);
    int tid  = threadIdx.x;
    int lane = tid & 31, wid = tid >> 5;
    int wm0 = (wid >> 1) * 32;
    int wn0 = (wid & 1) * 64;

    int e = g_tileE[tileIdx], row0 = g_tileRow[tileIdx];
    int cnt = g_count[e], base = g_base[e];
    int n0 = blockIdx.x * BN;
    int mrem = cnt - row0;

    const __half* aH = (G2 ? g_hh : g_xh) + (size_t)(base + row0) * KD;
    const int brows = G2 ? HDIM : N2I;
    const __half* bH = (G2 ? g_wdh : g_w1h) + ((size_t)e * brows + n0) * KD;
    const __half* bL = (G2 ? g_wdl : g_w1l) + ((size_t)e * brows + n0) * KD;

    auto load_stage = [&](int buf, int k0) {
        uint32_t s0 = sb + buf * STAGEB;
#pragma unroll
        for (int i = 0; i < 4; i++) {
            int q = tid + i * 256;
            int row = q >> 3, c = q & 7;
            uint32_t so = row * ROWB + c * 16;
            size_t go = (size_t)row * KD + k0 + c * 8;
            bool v = row < mrem;
            cp16(s0 + O_AH + so, aH + go, v);
            cp16(s0 + O_BH + so, bH + go, true);
            cp16(s0 + O_BL + so, bL + go, true);
        }
        asm volatile("cp.async.commit_group;" ::: "memory");
    };

    float acc[2][8][4];
#pragma unroll
    for (int a = 0; a < 2; a++)
#pragma unroll
        for (int b = 0; b < 8; b++)
#pragma unroll
            for (int c = 0; c < 4; c++) acc[a][b][c] = 0.f;

    int lr = lane & 7, lt = lane >> 3;
    int rowoff  = lr + (lt & 1) * 8;
    int bytesel = (lt >> 1) * 16;

    uint32_t ah[2][4];     // A frags, current ks
    uint32_t bb[2][8];     // B frags, double-buffered: [0..3]=bh, [4..7]=bl

    const int STAGES = KD / BKH;
    load_stage(0, 0);
    for (int s = 0; s < STAGES; s++) {
        if (s + 1 < STAGES) {
            load_stage((s + 1) & 1, (s + 1) * BKH);
            asm volatile("cp.async.wait_group 1;" ::: "memory");
        } else {
            asm volatile("cp.async.wait_group 0;" ::: "memory");
        }
        __syncthreads();

        uint32_t s0 = sb + (s & 1) * STAGEB;
        uint32_t aBase = s0 + O_AH + (wm0 + rowoff) * ROWB + bytesel;
        uint32_t bBaseH = s0 + O_BH + (wn0 + rowoff) * ROWB + bytesel;
        uint32_t bBaseL = s0 + O_BL + (wn0 + rowoff) * ROWB + bytesel;

        // preload ks=0 fragments
        ldsm4(ah[0], aBase);
        ldsm4(ah[1], aBase + 16 * ROWB);
        ldsm4(&bb[0][0], bBaseH);
        ldsm4(&bb[0][4], bBaseL);

#pragma unroll
        for (int ks = 0; ks < 4; ks++) {
#pragma unroll
            for (int ng = 0; ng < 4; ng++) {
                const int cur = (ks * 4 + ng) & 1;
                // prefetch next B fragment pair (and next A at ks boundary)
                if (ng < 3) {
                    uint32_t rb = (ng + 1) * 16 * ROWB + ks * 32;
                    ldsm4(&bb[cur ^ 1][0], bBaseH + rb);
                    ldsm4(&bb[cur ^ 1][4], bBaseL + rb);
                } else if (ks < 3) {
                    uint32_t rb = (ks + 1) * 32;
                    ldsm4(&bb[cur ^ 1][0], bBaseH + rb);
                    ldsm4(&bb[cur ^ 1][4], bBaseL + rb);
                }
#pragma unroll
                for (int mt = 0; mt < 2; mt++) {
                    float* c0 = acc[mt][ng * 2];
                    float* c1 = acc[mt][ng * 2 + 1];
                    mma16816(c0, ah[mt], bb[cur][0], bb[cur][2]);
                    mma16816(c1, ah[mt], bb[cur][1], bb[cur][3]);
                    mma16816(c0, ah[mt], bb[cur][4], bb[cur][6]);
                    mma16816(c1, ah[mt], bb[cur][5], bb[cur][7]);
                }
            }
            if (ks < 3) {   // next ks A fragments (issued after consumers of ah)
                ldsm4(ah[0], aBase + (ks + 1) * 32);
                ldsm4(ah[1], aBase + 16 * ROWB + (ks + 1) * 32);
            }
        }
        __syncthreads();
    }

    // ---------------- epilogue ----------------
    if (G2) {
        int gcol = n0 + wn0 + (lane & 3) * 2;
#pragma unroll
        for (int mt = 0; mt < 2; mt++) {
#pragma unroll
            for (int half = 0; half < 2; half++) {
                int rloc = wm0 + mt * 16 + (lane >> 2) + half * 8;
                if (rloc >= mrem) continue;
                int gr = row0 + rloc;
                float wscale = g_wt[e * T_TOK + gr];
                int   tok    = g_list[e * T_TOK + gr];
                float* outp = out + (size_t)tok * HDIM + gcol;
#pragma unroll
                for (int nt = 0; nt < 8; nt++) {
                    atomicAdd(outp + nt * 8 + 0, acc[mt][nt][half * 2 + 0] * wscale);
                    atomicAdd(outp + nt * 8 + 1, acc[mt][nt][half * 2 + 1] * wscale);
                }
            }
        }
    } else {
        // interleaved cols: even=gate_i, odd=up_i ; pair index in I-space
        int pairBase = (n0 >> 1) + (wn0 >> 1) + (lane & 3);
#pragma unroll
        for (int mt = 0; mt < 2; mt++) {
#pragma unroll
            for (int half = 0; half < 2; half++) {
                int rloc = wm0 + mt * 16 + (lane >> 2) + half * 8;
                if (rloc >= mrem) continue;
                __half* dst = g_hh + (size_t)(base + row0 + rloc) * IDIM + pairBase;
#pragma unroll
                for (int nt = 0; nt < 8; nt++) {
                    float g = acc[mt][nt][half * 2 + 0];
                    float u = acc[mt][nt][half * 2 + 1];
                    float h = g / (1.f + expf(-g)) * u;
                    dst[nt * 4] = __float2half_rn(h);
                }
            }
        }
    }
}

// ---------------- launch --------------------------------------------------
extern "C" void kernel_launch(void* const* d_in, const int* in_sizes, int n_in,
                              void* d_out, int out_size) {
    const float* x  = (const float*)d_in[0];
    const float* rw = (const float*)d_in[1];
    const float* wg = (const float*)d_in[2];
    const float* wu = (const float*)d_in[3];
    const float* wd = (const float*)d_in[4];
    float* out = (float*)d_out;

    cudaFuncSetAttribute(k_gemm<HDIM, false>,
                         cudaFuncAttributeMaxDynamicSharedMemorySize, SMEM_TOTAL);
    cudaFuncSetAttribute(k_gemm<IDIM, true>,
                         cudaFuncAttributeMaxDynamicSharedMemorySize, SMEM_TOTAL);

    k_init<<<1, 32>>>();
    k_zero<<<(T_TOK * HDIM / 4 + 255) / 256, 256>>>(out);
    k_router<<<T_TOK / 8, 256>>>(x, rw);
    k_build<<<1, 1>>>();

    const size_t WG = (size_t)NEXP * IDIM * HDIM;
    const size_t WD = (size_t)NEXP * HDIM * IDIM;
    unsigned splitBlocks = (unsigned)(((2 * WG + WD) / 4 + 255) / 256);
    k_splitw<<<splitBlocks, 256>>>(wg, wu, wd);

    k_gather<<<NPAIR, 128>>>(x);

    dim3 g1(N2I / BN, MAXT);   // (22, 72)
    k_gemm<HDIM, false><<<g1, 256, SMEM_TOTAL>>>(nullptr);

    dim3 g2(HDIM / BN, MAXT);  // (8, 72)
    k_gemm<IDIM, true><<<g2, 256, SMEM_TOTAL>>>(out);
}

// round 10
// speedup vs baseline: 1.7015x; 1.7015x over previous
#include <cuda_runtime.h>
#include <cuda_fp16.h>
#include <math.h>
#include <stdint.h>

#define T_TOK 4096
#define HDIM  1024
#define IDIM  1408
#define NEXP  8
#define NPAIR (T_TOK * 2)
#define N2I   (2 * IDIM)           // 2816 (interleaved gate/up rows)
#define BM 128
#define BN 128
#define BKH 64                     // K halves per stage (128B rows)
#define MAXT 72

// smem: rows 128B data + 16B pad = 144B (ldmatrix stride 36 words -> conflict-free)
#define ROWB 144
#define REG  (128 * ROWB)          // 18432 B per operand region

// ---------------- scratch (static device globals; no allocations) ----------
__device__ int   g_count[NEXP];
__device__ int   g_list [NEXP * T_TOK];
__device__ float g_wt   [NEXP * T_TOK];
__device__ int   g_slot [NEXP * T_TOK];
__device__ int   g_base [NEXP];
__device__ int   g_tileE[MAXT];
__device__ int   g_tileRow[MAXT];
__device__ int   g_numTiles;

__device__ __half g_xh [(size_t)NPAIR * HDIM];
__device__ __half g_w1h[(size_t)NEXP * N2I * HDIM];   // interleaved: row 2i=gate_i, 2i+1=up_i
__device__ __half g_w1l[(size_t)NEXP * N2I * HDIM];
__device__ __half g_wdh[(size_t)NEXP * HDIM * IDIM];
__device__ __half g_hh [(size_t)NPAIR * IDIM];
__device__ float  g_y  [(size_t)NPAIR * HDIM];

// ---------------- helpers -------------------------------------------------
__device__ __forceinline__ uint32_t smem_u32(const void* p) {
    uint32_t a;
    asm("{ .reg .u64 t; cvta.to.shared.u64 t, %1; cvt.u32.u64 %0, t; }" : "=r"(a) : "l"(p));
    return a;
}
__device__ __forceinline__ void cp16(uint32_t s, const void* g, bool v) {
    int sz = v ? 16 : 0;
    asm volatile("cp.async.cg.shared.global [%0], [%1], 16, %2;" :: "r"(s), "l"(g), "r"(sz) : "memory");
}
__device__ __forceinline__ void ldsm4(uint32_t* r, uint32_t addr) {
    asm volatile("ldmatrix.sync.aligned.m8n8.x4.shared.b16 {%0,%1,%2,%3}, [%4];"
                 : "=r"(r[0]), "=r"(r[1]), "=r"(r[2]), "=r"(r[3]) : "r"(addr));
}
__device__ __forceinline__ void mma16816(float* c, const uint32_t* a, uint32_t b0, uint32_t b1) {
    asm volatile("mma.sync.aligned.m16n8k16.row.col.f32.f16.f16.f32 "
                 "{%0,%1,%2,%3}, {%4,%5,%6,%7}, {%8,%9}, {%0,%1,%2,%3};"
                 : "+f"(c[0]), "+f"(c[1]), "+f"(c[2]), "+f"(c[3])
                 : "r"(a[0]), "r"(a[1]), "r"(a[2]), "r"(a[3]), "r"(b0), "r"(b1));
}
__device__ __forceinline__ void split_store(float4 v, __half* hp, __half* lp) {
    __half h0 = __float2half_rn(v.x), h1 = __float2half_rn(v.y);
    __half h2 = __float2half_rn(v.z), h3 = __float2half_rn(v.w);
    __half l0 = __float2half_rn(v.x - __half2float(h0));
    __half l1 = __float2half_rn(v.y - __half2float(h1));
    __half l2 = __float2half_rn(v.z - __half2float(h2));
    __half l3 = __float2half_rn(v.w - __half2float(h3));
    ((__half2*)hp)[0] = __halves2half2(h0, h1);
    ((__half2*)hp)[1] = __halves2half2(h2, h3);
    ((__half2*)lp)[0] = __halves2half2(l0, l1);
    ((__half2*)lp)[1] = __halves2half2(l2, l3);
}

// ---------------- init ----------------------------------------------------
__global__ void k_init() {
    if (threadIdx.x < NEXP) g_count[threadIdx.x] = 0;
}

// ---------------- router: one warp per token ------------------------------
__global__ void k_router(const float* __restrict__ x, const float* __restrict__ rw) {
    int warp = (blockIdx.x * blockDim.x + threadIdx.x) >> 5;
    int lane = threadIdx.x & 31;
    if (warp >= T_TOK) return;
    const float* xr = x + (size_t)warp * HDIM;

    float xv[32];
#pragma unroll
    for (int j = 0; j < 32; j++) xv[j] = xr[lane + j * 32];

    float logits[NEXP];
#pragma unroll
    for (int e = 0; e < NEXP; e++) {
        const float* wr = rw + (size_t)e * HDIM;
        float acc = 0.f;
#pragma unroll
        for (int j = 0; j < 32; j++) acc += xv[j] * wr[lane + j * 32];
#pragma unroll
        for (int s = 16; s > 0; s >>= 1) acc += __shfl_xor_sync(0xffffffffu, acc, s);
        logits[e] = acc;
    }

    if (lane == 0) {
        int e1 = 0;
#pragma unroll
        for (int e = 1; e < NEXP; e++) if (logits[e] > logits[e1]) e1 = e;
        int e2 = (e1 == 0) ? 1 : 0;
#pragma unroll
        for (int e = 0; e < NEXP; e++)
            if (e != e1 && logits[e] > logits[e2]) e2 = e;
        float t  = expf(logits[e2] - logits[e1]);
        float w1 = 1.f / (1.f + t);
        float w2 = t   / (1.f + t);

        int i1 = atomicAdd(&g_count[e1], 1);
        g_list[e1 * T_TOK + i1] = warp;
        g_wt  [e1 * T_TOK + i1] = w1;
        g_slot[e1 * T_TOK + i1] = 2 * warp + 0;

        int i2 = atomicAdd(&g_count[e2], 1);
        g_list[e2 * T_TOK + i2] = warp;
        g_wt  [e2 * T_TOK + i2] = w2;
        g_slot[e2 * T_TOK + i2] = 2 * warp + 1;
    }
}

// ---------------- tile table ---------------------------------------------
__global__ void k_build() {
    if (threadIdx.x != 0 || blockIdx.x != 0) return;
    int base = 0, nt = 0;
    for (int e = 0; e < NEXP; e++) {
        g_base[e] = base;
        int c = g_count[e];
        int tiles = (c + BM - 1) / BM;
        for (int r = 0; r < tiles; r++) {
            g_tileE[nt]   = e;
            g_tileRow[nt] = r * BM;
            nt++;
        }
        base += c;
    }
    g_numTiles = nt;
}

// ---------------- weight split: w1 -> (hi,lo) interleaved; wd -> hi only --
__global__ void k_splitw(const float* __restrict__ wg, const float* __restrict__ wu,
                         const float* __restrict__ wd) {
    const size_t WG = (size_t)NEXP * IDIM * HDIM;
    const size_t WD = (size_t)NEXP * HDIM * IDIM;
    size_t idx4 = (size_t)blockIdx.x * blockDim.x + threadIdx.x;
    size_t f = idx4 * 4;
    if (f < WG) {                       // gate -> row 2i
        size_t e = f / ((size_t)IDIM * HDIM);
        size_t r = f % ((size_t)IDIM * HDIM);
        size_t i = r / HDIM, k = r % HDIM;
        float4 v = *(const float4*)(wg + f);
        size_t dst = ((size_t)e * N2I + 2 * i) * HDIM + k;
        split_store(v, g_w1h + dst, g_w1l + dst);
    } else if (f < 2 * WG) {            // up -> row 2i+1
        size_t f2 = f - WG;
        size_t e = f2 / ((size_t)IDIM * HDIM);
        size_t r = f2 % ((size_t)IDIM * HDIM);
        size_t i = r / HDIM, k = r % HDIM;
        float4 v = *(const float4*)(wu + f2);
        size_t dst = ((size_t)e * N2I + 2 * i + 1) * HDIM + k;
        split_store(v, g_w1h + dst, g_w1l + dst);
    } else if (f < 2 * WG + WD) {       // down, linear, hi only
        size_t f2 = f - 2 * WG;
        float4 v = *(const float4*)(wd + f2);
        __half* hp = g_wdh + f2;
        ((__half2*)hp)[0] = __halves2half2(__float2half_rn(v.x), __float2half_rn(v.y));
        ((__half2*)hp)[1] = __halves2half2(__float2half_rn(v.z), __float2half_rn(v.w));
    }
}

// ---------------- gather: fp32 rows -> fp16 hi, sorted order --------------
__global__ void k_gather(const float* __restrict__ x) {
    int p = blockIdx.x;
    int e = 0;
#pragma unroll
    for (int i = 0; i < NEXP; i++)
        if (p >= g_base[i] && p < g_base[i] + g_count[i]) e = i;
    int r   = p - g_base[e];
    int tok = g_list[e * T_TOK + r];
    const float* src = x + (size_t)tok * HDIM;
    __half* dst = g_xh + (size_t)p * HDIM;
    for (int c = threadIdx.x * 4; c < HDIM; c += blockDim.x * 4) {
        float4 v = *(const float4*)(src + c);
        ((__half2*)(dst + c))[0] = __halves2half2(__float2half_rn(v.x), __float2half_rn(v.y));
        ((__half2*)(dst + c))[1] = __halves2half2(__float2half_rn(v.z), __float2half_rn(v.w));
    }
}

// ---------------- split-fp16 HMMA GEMM ------------------------------------
// G1 (2-term B): C = Ah @ (Bh+Bl)^T, fused silu(gate)*up -> g_hh
// G2 (1-term B): C = Ah @ Bh^T, scaled scatter -> g_y
template <int KD, bool G2>
__global__ void __launch_bounds__(256, 2) k_gemm() {
    constexpr int NREGS   = G2 ? 2 : 3;
    constexpr uint32_t STAGEB = NREGS * REG;
    constexpr uint32_t O_AH = 0, O_BH = REG, O_BL = 2 * REG;

    int tileIdx = blockIdx.y;
    if (tileIdx >= g_numTiles) return;
    extern __shared__ char smem[];
    uint32_t sb = smem_u32(smem);
    int tid  = threadIdx.x;
    int lane = tid & 31, wid = tid >> 5;
    int wm0 = (wid >> 1) * 32;
    int wn0 = (wid & 1) * 64;

    int e = g_tileE[tileIdx], row0 = g_tileRow[tileIdx];
    int cnt = g_count[e], base = g_base[e];
    int n0 = blockIdx.x * BN;
    int mrem = cnt - row0;

    const __half* aH = (G2 ? g_hh : g_xh) + (size_t)(base + row0) * KD;
    const int brows = G2 ? HDIM : N2I;
    const __half* bH = (G2 ? g_wdh : g_w1h) + ((size_t)e * brows + n0) * KD;
    const __half* bL = G2 ? nullptr : (g_w1l + ((size_t)e * brows + n0) * KD);

    auto load_stage = [&](int buf, int k0) {
        uint32_t s0 = sb + buf * STAGEB;
#pragma unroll
        for (int i = 0; i < 4; i++) {
            int q = tid + i * 256;
            int row = q >> 3, c = q & 7;
            uint32_t so = row * ROWB + c * 16;
            size_t go = (size_t)row * KD + k0 + c * 8;
            bool v = row < mrem;
            cp16(s0 + O_AH + so, aH + go, v);
            cp16(s0 + O_BH + so, bH + go, true);
            if (!G2) cp16(s0 + O_BL + so, bL + go, true);
        }
        asm volatile("cp.async.commit_group;" ::: "memory");
    };

    float acc[2][8][4];
#pragma unroll
    for (int a = 0; a < 2; a++)
#pragma unroll
        for (int b = 0; b < 8; b++)
#pragma unroll
            for (int c = 0; c < 4; c++) acc[a][b][c] = 0.f;

    int lr = lane & 7, lt = lane >> 3;
    int rowoff  = lr + (lt & 1) * 8;
    int bytesel = (lt >> 1) * 16;

    const int STAGES = KD / BKH;
    load_stage(0, 0);
    for (int s = 0; s < STAGES; s++) {
        if (s + 1 < STAGES) {
            load_stage((s + 1) & 1, (s + 1) * BKH);
            asm volatile("cp.async.wait_group 1;" ::: "memory");
        } else {
            asm volatile("cp.async.wait_group 0;" ::: "memory");
        }
        __syncthreads();

        uint32_t s0 = sb + (s & 1) * STAGEB;
#pragma unroll
        for (int ks = 0; ks < 4; ks++) {
            uint32_t kb = ks * 32 + bytesel;
            uint32_t ah[2][4];
#pragma unroll
            for (int mt = 0; mt < 2; mt++)
                ldsm4(ah[mt], s0 + O_AH + (wm0 + mt * 16 + rowoff) * ROWB + kb);
#pragma unroll
            for (int ng = 0; ng < 4; ng++) {
                uint32_t rb = (wn0 + ng * 16 + rowoff) * ROWB + kb;
                uint32_t bh[4];
                ldsm4(bh, s0 + O_BH + rb);
                if (!G2) {
                    uint32_t bl[4];
                    ldsm4(bl, s0 + O_BL + rb);
#pragma unroll
                    for (int mt = 0; mt < 2; mt++) {
                        float* c0 = acc[mt][ng * 2];
                        float* c1 = acc[mt][ng * 2 + 1];
                        mma16816(c0, ah[mt], bh[0], bh[2]);
                        mma16816(c1, ah[mt], bh[1], bh[3]);
                        mma16816(c0, ah[mt], bl[0], bl[2]);
                        mma16816(c1, ah[mt], bl[1], bl[3]);
                    }
                } else {
#pragma unroll
                    for (int mt = 0; mt < 2; mt++) {
                        float* c0 = acc[mt][ng * 2];
                        float* c1 = acc[mt][ng * 2 + 1];
                        mma16816(c0, ah[mt], bh[0], bh[2]);
                        mma16816(c1, ah[mt], bh[1], bh[3]);
                    }
                }
            }
        }
        __syncthreads();
    }

    // ---------------- epilogue ----------------
    if (G2) {
        int gcol = n0 + wn0 + (lane & 3) * 2;
#pragma unroll
        for (int mt = 0; mt < 2; mt++) {
#pragma unroll
            for (int half = 0; half < 2; half++) {
                int rloc = wm0 + mt * 16 + (lane >> 2) + half * 8;
                if (rloc >= mrem) continue;
                int gr = row0 + rloc;
                float wscale  = g_wt[e * T_TOK + gr];
                float* outp = g_y + (size_t)g_slot[e * T_TOK + gr] * HDIM + gcol;
#pragma unroll
                for (int nt = 0; nt < 8; nt++) {
                    float2 v;
                    v.x = acc[mt][nt][half * 2 + 0] * wscale;
                    v.y = acc[mt][nt][half * 2 + 1] * wscale;
                    *(float2*)(outp + nt * 8) = v;
                }
            }
        }
    } else {
        // interleaved cols: even=gate_i, odd=up_i ; pair index in I-space
        int pairBase = (n0 >> 1) + (wn0 >> 1) + (lane & 3);
#pragma unroll
        for (int mt = 0; mt < 2; mt++) {
#pragma unroll
            for (int half = 0; half < 2; half++) {
                int rloc = wm0 + mt * 16 + (lane >> 2) + half * 8;
                if (rloc >= mrem) continue;
                __half* dst = g_hh + (size_t)(base + row0 + rloc) * IDIM + pairBase;
#pragma unroll
                for (int nt = 0; nt < 8; nt++) {
                    float g = acc[mt][nt][half * 2 + 0];
                    float u = acc[mt][nt][half * 2 + 1];
                    float h = g / (1.f + expf(-g)) * u;
                    dst[nt * 4] = __float2half_rn(h);
                }
            }
        }
    }
}

// ---------------- reduce: out[t] = y[2t] + y[2t+1] ------------------------
__global__ void k_reduce(float* __restrict__ out) {
    size_t idx = (size_t)blockIdx.x * blockDim.x + threadIdx.x;
    size_t total = (size_t)T_TOK * HDIM / 4;
    if (idx >= total) return;
    size_t t = idx / (HDIM / 4);
    size_t c = idx % (HDIM / 4);
    const float4 a = *(const float4*)&g_y[(2 * t)     * HDIM + c * 4];
    const float4 b = *(const float4*)&g_y[(2 * t + 1) * HDIM + c * 4];
    float4 o = make_float4(a.x + b.x, a.y + b.y, a.z + b.z, a.w + b.w);
    *(float4*)&out[idx * 4] = o;
}

// ---------------- launch --------------------------------------------------
extern "C" void kernel_launch(void* const* d_in, const int* in_sizes, int n_in,
                              void* d_out, int out_size) {
    const float* x  = (const float*)d_in[0];
    const float* rw = (const float*)d_in[1];
    const float* wg = (const float*)d_in[2];
    const float* wu = (const float*)d_in[3];
    const float* wd = (const float*)d_in[4];
    float* out = (float*)d_out;

    const unsigned SMEM_G1 = 2 * 3 * REG;   // 110592
    const unsigned SMEM_G2 = 2 * 2 * REG;   // 73728

    cudaFuncSetAttribute(k_gemm<HDIM, false>,
                         cudaFuncAttributeMaxDynamicSharedMemorySize, SMEM_G1);
    cudaFuncSetAttribute(k_gemm<IDIM, true>,
                         cudaFuncAttributeMaxDynamicSharedMemorySize, SMEM_G2);

    k_init<<<1, 32>>>();
    k_router<<<T_TOK / 8, 256>>>(x, rw);
    k_build<<<1, 1>>>();

    const size_t WG = (size_t)NEXP * IDIM * HDIM;
    const size_t WD = (size_t)NEXP * HDIM * IDIM;
    unsigned splitBlocks = (unsigned)(((2 * WG + WD) / 4 + 255) / 256);
    k_splitw<<<splitBlocks, 256>>>(wg, wu, wd);

    k_gather<<<NPAIR, 128>>>(x);

    dim3 g1(N2I / BN, MAXT);   // (22, 72)
    k_gemm<HDIM, false><<<g1, 256, SMEM_G1>>>();

    dim3 g2(HDIM / BN, MAXT);  // (8, 72)
    k_gemm<IDIM, true><<<g2, 256, SMEM_G2>>>();

    size_t redN = (size_t)T_TOK * HDIM / 4;
    k_reduce<<<(unsigned)((redN + 255) / 256), 256>>>(out);
}

// round 12
// speedup vs baseline: 2.3140x; 1.3600x over previous
#include <cuda_runtime.h>
#include <cuda_fp16.h>
#include <math.h>
#include <stdint.h>

#define T_TOK 4096
#define HDIM  1024
#define IDIM  1408
#define NEXP  8
#define NPAIR (T_TOK * 2)
#define N2I   (2 * IDIM)           // 2816 (interleaved gate/up rows)
#define BM 128
#define BN 128
#define BKH 64                     // K halves per stage (128B rows)
#define MAXT 72

// smem: rows 128B data + 16B pad = 144B (ldmatrix stride 36 words -> conflict-free)
#define ROWB 144
#define REG  (128 * ROWB)          // 18432 B per operand region
#define STAGEB (2 * REG)           // A + B = 36864
#define SMEM_TOTAL (2 * STAGEB)    // 73728 (double-buffered) -> 2 CTAs/SM

// ---------------- scratch (static device globals; no allocations) ----------
__device__ int   g_count[NEXP];
__device__ int   g_list [NEXP * T_TOK];
__device__ float g_wt   [NEXP * T_TOK];
__device__ int   g_slot [NEXP * T_TOK];
__device__ int   g_base [NEXP];
__device__ int   g_tileE[MAXT];
__device__ int   g_tileRow[MAXT];
__device__ int   g_numTiles;

__device__ __half g_xh [(size_t)NPAIR * HDIM];
__device__ __half g_w1h[(size_t)NEXP * N2I * HDIM];   // interleaved: row 2i=gate_i, 2i+1=up_i
__device__ __half g_wdh[(size_t)NEXP * HDIM * IDIM];
__device__ __half g_hh [(size_t)NPAIR * IDIM];
__device__ float  g_y  [(size_t)NPAIR * HDIM];

// ---------------- helpers -------------------------------------------------
__device__ __forceinline__ uint32_t smem_u32(const void* p) {
    uint32_t a;
    asm("{ .reg .u64 t; cvta.to.shared.u64 t, %1; cvt.u32.u64 %0, t; }" : "=r"(a) : "l"(p));
    return a;
}
__device__ __forceinline__ void cp16(uint32_t s, const void* g, bool v) {
    int sz = v ? 16 : 0;
    asm volatile("cp.async.cg.shared.global [%0], [%1], 16, %2;" :: "r"(s), "l"(g), "r"(sz) : "memory");
}
__device__ __forceinline__ void ldsm4(uint32_t* r, uint32_t addr) {
    asm volatile("ldmatrix.sync.aligned.m8n8.x4.shared.b16 {%0,%1,%2,%3}, [%4];"
                 : "=r"(r[0]), "=r"(r[1]), "=r"(r[2]), "=r"(r[3]) : "r"(addr));
}
__device__ __forceinline__ void mma16816(float* c, const uint32_t* a, uint32_t b0, uint32_t b1) {
    asm volatile("mma.sync.aligned.m16n8k16.row.col.f32.f16.f16.f32 "
                 "{%0,%1,%2,%3}, {%4,%5,%6,%7}, {%8,%9}, {%0,%1,%2,%3};"
                 : "+f"(c[0]), "+f"(c[1]), "+f"(c[2]), "+f"(c[3])
                 : "r"(a[0]), "r"(a[1]), "r"(a[2]), "r"(a[3]), "r"(b0), "r"(b1));
}
__device__ __forceinline__ void h_store4(float4 v, __half* hp) {
    ((__half2*)hp)[0] = __halves2half2(__float2half_rn(v.x), __float2half_rn(v.y));
    ((__half2*)hp)[1] = __halves2half2(__float2half_rn(v.z), __float2half_rn(v.w));
}

// ---------------- init ----------------------------------------------------
__global__ void k_init() {
    if (threadIdx.x < NEXP) g_count[threadIdx.x] = 0;
}

// ---------------- router: one warp per token ------------------------------
__global__ void k_router(const float* __restrict__ x, const float* __restrict__ rw) {
    int warp = (blockIdx.x * blockDim.x + threadIdx.x) >> 5;
    int lane = threadIdx.x & 31;
    if (warp >= T_TOK) return;
    const float* xr = x + (size_t)warp * HDIM;

    float xv[32];
#pragma unroll
    for (int j = 0; j < 32; j++) xv[j] = xr[lane + j * 32];

    float logits[NEXP];
#pragma unroll
    for (int e = 0; e < NEXP; e++) {
        const float* wr = rw + (size_t)e * HDIM;
        float acc = 0.f;
#pragma unroll
        for (int j = 0; j < 32; j++) acc += xv[j] * wr[lane + j * 32];
#pragma unroll
        for (int s = 16; s > 0; s >>= 1) acc += __shfl_xor_sync(0xffffffffu, acc, s);
        logits[e] = acc;
    }

    if (lane == 0) {
        int e1 = 0;
#pragma unroll
        for (int e = 1; e < NEXP; e++) if (logits[e] > logits[e1]) e1 = e;
        int e2 = (e1 == 0) ? 1 : 0;
#pragma unroll
        for (int e = 0; e < NEXP; e++)
            if (e != e1 && logits[e] > logits[e2]) e2 = e;
        float t  = expf(logits[e2] - logits[e1]);
        float w1 = 1.f / (1.f + t);
        float w2 = t   / (1.f + t);

        int i1 = atomicAdd(&g_count[e1], 1);
        g_list[e1 * T_TOK + i1] = warp;
        g_wt  [e1 * T_TOK + i1] = w1;
        g_slot[e1 * T_TOK + i1] = 2 * warp + 0;

        int i2 = atomicAdd(&g_count[e2], 1);
        g_list[e2 * T_TOK + i2] = warp;
        g_wt  [e2 * T_TOK + i2] = w2;
        g_slot[e2 * T_TOK + i2] = 2 * warp + 1;
    }
}

// ---------------- tile table ---------------------------------------------
__global__ void k_build() {
    if (threadIdx.x != 0 || blockIdx.x != 0) return;
    int base = 0, nt = 0;
    for (int e = 0; e < NEXP; e++) {
        g_base[e] = base;
        int c = g_count[e];
        int tiles = (c + BM - 1) / BM;
        for (int r = 0; r < tiles; r++) {
            g_tileE[nt]   = e;
            g_tileRow[nt] = r * BM;
            nt++;
        }
        base += c;
    }
    g_numTiles = nt;
}

// ---------------- weight convert: fp32 -> fp16 hi, interleave gate/up -----
__global__ void k_splitw(const float* __restrict__ wg, const float* __restrict__ wu,
                         const float* __restrict__ wd) {
    const size_t WG = (size_t)NEXP * IDIM * HDIM;
    const size_t WD = (size_t)NEXP * HDIM * IDIM;
    size_t idx4 = (size_t)blockIdx.x * blockDim.x + threadIdx.x;
    size_t f = idx4 * 4;
    if (f < WG) {                       // gate -> row 2i
        size_t e = f / ((size_t)IDIM * HDIM);
        size_t r = f % ((size_t)IDIM * HDIM);
        size_t i = r / HDIM, k = r % HDIM;
        float4 v = *(const float4*)(wg + f);
        h_store4(v, g_w1h + ((size_t)e * N2I + 2 * i) * HDIM + k);
    } else if (f < 2 * WG) {            // up -> row 2i+1
        size_t f2 = f - WG;
        size_t e = f2 / ((size_t)IDIM * HDIM);
        size_t r = f2 % ((size_t)IDIM * HDIM);
        size_t i = r / HDIM, k = r % HDIM;
        float4 v = *(const float4*)(wu + f2);
        h_store4(v, g_w1h + ((size_t)e * N2I + 2 * i + 1) * HDIM + k);
    } else if (f < 2 * WG + WD) {       // down, linear
        size_t f2 = f - 2 * WG;
        float4 v = *(const float4*)(wd + f2);
        h_store4(v, g_wdh + f2);
    }
}

// ---------------- gather: fp32 rows -> fp16, sorted order -----------------
__global__ void k_gather(const float* __restrict__ x) {
    int p = blockIdx.x;
    int e = 0;
#pragma unroll
    for (int i = 0; i < NEXP; i++)
        if (p >= g_base[i] && p < g_base[i] + g_count[i]) e = i;
    int r   = p - g_base[e];
    int tok = g_list[e * T_TOK + r];
    const float* src = x + (size_t)tok * HDIM;
    __half* dst = g_xh + (size_t)p * HDIM;
    for (int c = threadIdx.x * 4; c < HDIM; c += blockDim.x * 4) {
        float4 v = *(const float4*)(src + c);
        h_store4(v, dst + c);
    }
}

// ---------------- fp16 HMMA GEMM ------------------------------------------
// G1: C = Ah @ B1^T, fused silu(gate)*up -> g_hh (interleaved cols)
// G2: C = Ah @ Bd^T, scaled scatter -> g_y
template <int KD, bool G2>
__global__ void __launch_bounds__(256, 2) k_gemm() {
    constexpr uint32_t O_AH = 0, O_BH = REG;

    int tileIdx = blockIdx.y;
    if (tileIdx >= g_numTiles) return;
    extern __shared__ char smem[];
    uint32_t sb = smem_u32(smem);
    int tid  = threadIdx.x;
    int lane = tid & 31, wid = tid >> 5;
    int wm0 = (wid >> 1) * 32;
    int wn0 = (wid & 1) * 64;

    int e = g_tileE[tileIdx], row0 = g_tileRow[tileIdx];
    int cnt = g_count[e], base = g_base[e];
    int n0 = blockIdx.x * BN;
    int mrem = cnt - row0;

    const __half* aH = (G2 ? g_hh : g_xh) + (size_t)(base + row0) * KD;
    const int brows = G2 ? HDIM : N2I;
    const __half* bH = (G2 ? g_wdh : g_w1h) + ((size_t)e * brows + n0) * KD;

    auto load_stage = [&](int buf, int k0) {
        uint32_t s0 = sb + buf * STAGEB;
#pragma unroll
        for (int i = 0; i < 4; i++) {
            int q = tid + i * 256;
            int row = q >> 3, c = q & 7;
            uint32_t so = row * ROWB + c * 16;
            size_t go = (size_t)row * KD + k0 + c * 8;
            bool v = row < mrem;
            cp16(s0 + O_AH + so, aH + go, v);
            cp16(s0 + O_BH + so, bH + go, true);
        }
        asm volatile("cp.async.commit_group;" ::: "memory");
    };

    float acc[2][8][4];
#pragma unroll
    for (int a = 0; a < 2; a++)
#pragma unroll
        for (int b = 0; b < 8; b++)
#pragma unroll
            for (int c = 0; c < 4; c++) acc[a][b][c] = 0.f;

    int lr = lane & 7, lt = lane >> 3;
    int rowoff  = lr + (lt & 1) * 8;
    int bytesel = (lt >> 1) * 16;

    const int STAGES = KD / BKH;
    load_stage(0, 0);
    for (int s = 0; s < STAGES; s++) {
        if (s + 1 < STAGES) {
            load_stage((s + 1) & 1, (s + 1) * BKH);
            asm volatile("cp.async.wait_group 1;" ::: "memory");
        } else {
            asm volatile("cp.async.wait_group 0;" ::: "memory");
        }
        __syncthreads();

        uint32_t s0 = sb + (s & 1) * STAGEB;
#pragma unroll
        for (int ks = 0; ks < 4; ks++) {
            uint32_t kb = ks * 32 + bytesel;
            uint32_t ah[2][4];
#pragma unroll
            for (int mt = 0; mt < 2; mt++)
                ldsm4(ah[mt], s0 + O_AH + (wm0 + mt * 16 + rowoff) * ROWB + kb);
#pragma unroll
            for (int ng = 0; ng < 4; ng++) {
                uint32_t rb = (wn0 + ng * 16 + rowoff) * ROWB + kb;
                uint32_t bh[4];
                ldsm4(bh, s0 + O_BH + rb);
#pragma unroll
                for (int mt = 0; mt < 2; mt++) {
                    float* c0 = acc[mt][ng * 2];
                    float* c1 = acc[mt][ng * 2 + 1];
                    mma16816(c0, ah[mt], bh[0], bh[2]);
                    mma16816(c1, ah[mt], bh[1], bh[3]);
                }
            }
        }
        __syncthreads();
    }

    // ---------------- epilogue ----------------
    if (G2) {
        int gcol = n0 + wn0 + (lane & 3) * 2;
#pragma unroll
        for (int mt = 0; mt < 2; mt++) {
#pragma unroll
            for (int half = 0; half < 2; half++) {
                int rloc = wm0 + mt * 16 + (lane >> 2) + half * 8;
                if (rloc >= mrem) continue;
                int gr = row0 + rloc;
                float wscale  = g_wt[e * T_TOK + gr];
                float* outp = g_y + (size_t)g_slot[e * T_TOK + gr] * HDIM + gcol;
#pragma unroll
                for (int nt = 0; nt < 8; nt++) {
                    float2 v;
                    v.x = acc[mt][nt][half * 2 + 0] * wscale;
                    v.y = acc[mt][nt][half * 2 + 1] * wscale;
                    *(float2*)(outp + nt * 8) = v;
                }
            }
        }
    } else {
        // interleaved cols: even=gate_i, odd=up_i ; pair index in I-space
        int pairBase = (n0 >> 1) + (wn0 >> 1) + (lane & 3);
#pragma unroll
        for (int mt = 0; mt < 2; mt++) {
#pragma unroll
            for (int half = 0; half < 2; half++) {
                int rloc = wm0 + mt * 16 + (lane >> 2) + half * 8;
                if (rloc >= mrem) continue;
                __half* dst = g_hh + (size_t)(base + row0 + rloc) * IDIM + pairBase;
#pragma unroll
                for (int nt = 0; nt < 8; nt++) {
                    float g = acc[mt][nt][half * 2 + 0];
                    float u = acc[mt][nt][half * 2 + 1];
                    float h = g / (1.f + expf(-g)) * u;
                    dst[nt * 4] = __float2half_rn(h);
                }
            }
        }
    }
}

// ---------------- reduce: out[t] = y[2t] + y[2t+1] ------------------------
__global__ void k_reduce(float* __restrict__ out) {
    size_t idx = (size_t)blockIdx.x * blockDim.x + threadIdx.x;
    size_t total = (size_t)T_TOK * HDIM / 4;
    if (idx >= total) return;
    size_t t = idx / (HDIM / 4);
    size_t c = idx % (HDIM / 4);
    const float4 a = *(const float4*)&g_y[(2 * t)     * HDIM + c * 4];
    const float4 b = *(const float4*)&g_y[(2 * t + 1) * HDIM + c * 4];
    float4 o = make_float4(a.x + b.x, a.y + b.y, a.z + b.z, a.w + b.w);
    *(float4*)&out[idx * 4] = o;
}

// ---------------- launch --------------------------------------------------
extern "C" void kernel_launch(void* const* d_in, const int* in_sizes, int n_in,
                              void* d_out, int out_size) {
    const float* x  = (const float*)d_in[0];
    const float* rw = (const float*)d_in[1];
    const float* wg = (const float*)d_in[2];
    const float* wu = (const float*)d_in[3];
    const float* wd = (const float*)d_in[4];
    float* out = (float*)d_out;

    cudaFuncSetAttribute(k_gemm<HDIM, false>,
                         cudaFuncAttributeMaxDynamicSharedMemorySize, SMEM_TOTAL);
    cudaFuncSetAttribute(k_gemm<IDIM, true>,
                         cudaFuncAttributeMaxDynamicSharedMemorySize, SMEM_TOTAL);

    k_init<<<1, 32>>>();
    k_router<<<T_TOK / 8, 256>>>(x, rw);
    k_build<<<1, 1>>>();

    const size_t WG = (size_t)NEXP * IDIM * HDIM;
    const size_t WD = (size_t)NEXP * HDIM * IDIM;
    unsigned splitBlocks = (unsigned)(((2 * WG + WD) / 4 + 255) / 256);
    k_splitw<<<splitBlocks, 256>>>(wg, wu, wd);

    k_gather<<<NPAIR, 128>>>(x);

    dim3 g1(N2I / BN, MAXT);   // (22, 72)
    k_gemm<HDIM, false><<<g1, 256, SMEM_TOTAL>>>();

    dim3 g2(HDIM / BN, MAXT);  // (8, 72)
    k_gemm<IDIM, true><<<g2, 256, SMEM_TOTAL>>>();

    size_t redN = (size_t)T_TOK * HDIM / 4;
    k_reduce<<<(unsigned)((redN + 255) / 256), 256>>>(out);
}

// round 14
// speedup vs baseline: 2.3207x; 1.0029x over previous
#include <cuda_runtime.h>
#include <cuda_fp16.h>
#include <math.h>
#include <stdint.h>

#define T_TOK 4096
#define HDIM  1024
#define IDIM  1408
#define NEXP  8
#define NPAIR (T_TOK * 2)
#define N2I   (2 * IDIM)           // 2816 (interleaved gate/up rows)
#define BM 128
#define BN 128
#define BKH 64                     // K halves per stage (128B rows)
#define MAXT 72

// smem: rows 128B data + 16B pad = 144B (ldmatrix stride 36 words -> conflict-free)
#define ROWB 144
#define REG  (128 * ROWB)          // 18432 B per operand region
#define STAGEB (2 * REG)           // A + B = 36864
#define SMEM_TOTAL (3 * STAGEB)    // 110592 (triple-buffered) -> 2 CTAs/SM

// ---------------- scratch (static device globals; no allocations) ----------
__device__ int   g_count[NEXP];
__device__ int   g_list [NEXP * T_TOK];
__device__ float g_wt   [NEXP * T_TOK];
__device__ int   g_base [NEXP];
__device__ int   g_tileE[MAXT];
__device__ int   g_tileRow[MAXT];
__device__ int   g_numTiles;

__device__ __half g_xh [(size_t)NPAIR * HDIM];
__device__ __half g_w1h[(size_t)NEXP * N2I * HDIM];   // interleaved: row 2i=gate_i, 2i+1=up_i
__device__ __half g_wdh[(size_t)NEXP * HDIM * IDIM];
__device__ __half g_hh [(size_t)NPAIR * IDIM];

// ---------------- helpers -------------------------------------------------
__device__ __forceinline__ uint32_t smem_u32(const void* p) {
    uint32_t a;
    asm("{ .reg .u64 t; cvta.to.shared.u64 t, %1; cvt.u32.u64 %0, t; }" : "=r"(a) : "l"(p));
    return a;
}
__device__ __forceinline__ void cp16(uint32_t s, const void* g, bool v) {
    int sz = v ? 16 : 0;
    asm volatile("cp.async.cg.shared.global [%0], [%1], 16, %2;" :: "r"(s), "l"(g), "r"(sz) : "memory");
}
__device__ __forceinline__ void ldsm4(uint32_t* r, uint32_t addr) {
    asm volatile("ldmatrix.sync.aligned.m8n8.x4.shared.b16 {%0,%1,%2,%3}, [%4];"
                 : "=r"(r[0]), "=r"(r[1]), "=r"(r[2]), "=r"(r[3]) : "r"(addr));
}
__device__ __forceinline__ void mma16816(float* c, const uint32_t* a, uint32_t b0, uint32_t b1) {
    asm volatile("mma.sync.aligned.m16n8k16.row.col.f32.f16.f16.f32 "
                 "{%0,%1,%2,%3}, {%4,%5,%6,%7}, {%8,%9}, {%0,%1,%2,%3};"
                 : "+f"(c[0]), "+f"(c[1]), "+f"(c[2]), "+f"(c[3])
                 : "r"(a[0]), "r"(a[1]), "r"(a[2]), "r"(a[3]), "r"(b0), "r"(b1));
}
__device__ __forceinline__ void h_store4(float4 v, __half* hp) {
    ((__half2*)hp)[0] = __halves2half2(__float2half_rn(v.x), __float2half_rn(v.y));
    ((__half2*)hp)[1] = __halves2half2(__float2half_rn(v.z), __float2half_rn(v.w));
}

// ---------------- init ----------------------------------------------------
__global__ void k_init() {
    if (threadIdx.x < NEXP) g_count[threadIdx.x] = 0;
}

// ---------------- zero output (atomic-accumulate base) --------------------
__global__ void k_zero(float* __restrict__ out) {
    size_t idx = (size_t)blockIdx.x * blockDim.x + threadIdx.x;
    if (idx < (size_t)T_TOK * HDIM / 4)
        *(float4*)(out + idx * 4) = make_float4(0.f, 0.f, 0.f, 0.f);
}

// ---------------- router: one warp per token ------------------------------
__global__ void k_router(const float* __restrict__ x, const float* __restrict__ rw) {
    int warp = (blockIdx.x * blockDim.x + threadIdx.x) >> 5;
    int lane = threadIdx.x & 31;
    if (warp >= T_TOK) return;
    const float* xr = x + (size_t)warp * HDIM;

    float xv[32];
#pragma unroll
    for (int j = 0; j < 32; j++) xv[j] = xr[lane + j * 32];

    float logits[NEXP];
#pragma unroll
    for (int e = 0; e < NEXP; e++) {
        const float* wr = rw + (size_t)e * HDIM;
        float acc = 0.f;
#pragma unroll
        for (int j = 0; j < 32; j++) acc += xv[j] * wr[lane + j * 32];
#pragma unroll
        for (int s = 16; s > 0; s >>= 1) acc += __shfl_xor_sync(0xffffffffu, acc, s);
        logits[e] = acc;
    }

    if (lane == 0) {
        int e1 = 0;
#pragma unroll
        for (int e = 1; e < NEXP; e++) if (logits[e] > logits[e1]) e1 = e;
        int e2 = (e1 == 0) ? 1 : 0;
#pragma unroll
        for (int e = 0; e < NEXP; e++)
            if (e != e1 && logits[e] > logits[e2]) e2 = e;
        float t  = expf(logits[e2] - logits[e1]);
        float w1 = 1.f / (1.f + t);
        float w2 = t   / (1.f + t);

        int i1 = atomicAdd(&g_count[e1], 1);
        g_list[e1 * T_TOK + i1] = warp;
        g_wt  [e1 * T_TOK + i1] = w1;

        int i2 = atomicAdd(&g_count[e2], 1);
        g_list[e2 * T_TOK + i2] = warp;
        g_wt  [e2 * T_TOK + i2] = w2;
    }
}

// ---------------- tile table ---------------------------------------------
__global__ void k_build() {
    if (threadIdx.x != 0 || blockIdx.x != 0) return;
    int base = 0, nt = 0;
    for (int e = 0; e < NEXP; e++) {
        g_base[e] = base;
        int c = g_count[e];
        int tiles = (c + BM - 1) / BM;
        for (int r = 0; r < tiles; r++) {
            g_tileE[nt]   = e;
            g_tileRow[nt] = r * BM;
            nt++;
        }
        base += c;
    }
    g_numTiles = nt;
}

// ---------------- weight convert: fp32 -> fp16, interleave gate/up --------
__global__ void k_splitw(const float* __restrict__ wg, const float* __restrict__ wu,
                         const float* __restrict__ wd) {
    const size_t WG = (size_t)NEXP * IDIM * HDIM;
    const size_t WD = (size_t)NEXP * HDIM * IDIM;
    size_t idx4 = (size_t)blockIdx.x * blockDim.x + threadIdx.x;
    size_t f = idx4 * 4;
    if (f < WG) {                       // gate -> row 2i
        size_t e = f / ((size_t)IDIM * HDIM);
        size_t r = f % ((size_t)IDIM * HDIM);
        size_t i = r / HDIM, k = r % HDIM;
        float4 v = *(const float4*)(wg + f);
        h_store4(v, g_w1h + ((size_t)e * N2I + 2 * i) * HDIM + k);
    } else if (f < 2 * WG) {            // up -> row 2i+1
        size_t f2 = f - WG;
        size_t e = f2 / ((size_t)IDIM * HDIM);
        size_t r = f2 % ((size_t)IDIM * HDIM);
        size_t i = r / HDIM, k = r % HDIM;
        float4 v = *(const float4*)(wu + f2);
        h_store4(v, g_w1h + ((size_t)e * N2I + 2 * i + 1) * HDIM + k);
    } else if (f < 2 * WG + WD) {       // down, linear
        size_t f2 = f - 2 * WG;
        float4 v = *(const float4*)(wd + f2);
        h_store4(v, g_wdh + f2);
    }
}

// ---------------- gather: fp32 rows -> fp16, sorted order -----------------
__global__ void k_gather(const float* __restrict__ x) {
    int p = blockIdx.x;
    int e = 0;
#pragma unroll
    for (int i = 0; i < NEXP; i++)
        if (p >= g_base[i] && p < g_base[i] + g_count[i]) e = i;
    int r   = p - g_base[e];
    int tok = g_list[e * T_TOK + r];
    const float* src = x + (size_t)tok * HDIM;
    __half* dst = g_xh + (size_t)p * HDIM;
    for (int c = threadIdx.x * 4; c < HDIM; c += blockDim.x * 4) {
        float4 v = *(const float4*)(src + c);
        h_store4(v, dst + c);
    }
}

// ---------------- fp16 HMMA GEMM, 3-stage pipeline ------------------------
// G1: C = Ah @ B1^T, fused silu(gate)*up -> g_hh (interleaved cols)
// G2: C = Ah @ Bd^T, scaled atomic accumulate -> out
template <int KD, bool G2>
__global__ void __launch_bounds__(256, 2) k_gemm(float* __restrict__ out) {
    constexpr uint32_t O_AH = 0, O_BH = REG;

    int tileIdx = blockIdx.y;
    if (tileIdx >= g_numTiles) return;
    extern __shared__ char smem[];
    uint32_t sb = smem_u32(smem);
    int tid  = threadIdx.x;
    int lane = tid & 31, wid = tid >> 5;
    int wm0 = (wid >> 1) * 32;
    int wn0 = (wid & 1) * 64;

    int e = g_tileE[tileIdx], row0 = g_tileRow[tileIdx];
    int cnt = g_count[e], base = g_base[e];
    int n0 = blockIdx.x * BN;
    int mrem = cnt - row0;

    const __half* aH = (G2 ? g_hh : g_xh) + (size_t)(base + row0) * KD;
    const int brows = G2 ? HDIM : N2I;
    const __half* bH = (G2 ? g_wdh : g_w1h) + ((size_t)e * brows + n0) * KD;

    auto load_stage = [&](int buf, int k0) {
        uint32_t s0 = sb + buf * STAGEB;
#pragma unroll
        for (int i = 0; i < 4; i++) {
            int q = tid + i * 256;
            int row = q >> 3, c = q & 7;
            uint32_t so = row * ROWB + c * 16;
            size_t go = (size_t)row * KD + k0 + c * 8;
            bool v = row < mrem;
            cp16(s0 + O_AH + so, aH + go, v);
            cp16(s0 + O_BH + so, bH + go, true);
        }
        asm volatile("cp.async.commit_group;" ::: "memory");
    };

    float acc[2][8][4];
#pragma unroll
    for (int a = 0; a < 2; a++)
#pragma unroll
        for (int b = 0; b < 8; b++)
#pragma unroll
            for (int c = 0; c < 4; c++) acc[a][b][c] = 0.f;

    int lr = lane & 7, lt = lane >> 3;
    int rowoff  = lr + (lt & 1) * 8;
    int bytesel = (lt >> 1) * 16;

    const int STAGES = KD / BKH;
    load_stage(0, 0);
    load_stage(1, BKH);
    int cb = 0, nb = 2;                 // compute buf, next load buf
    for (int s = 0; s < STAGES; s++) {
        asm volatile("cp.async.wait_group 1;" ::: "memory");
        __syncthreads();
        if (s + 2 < STAGES) load_stage(nb, (s + 2) * BKH);
        else asm volatile("cp.async.commit_group;" ::: "memory");

        uint32_t s0 = sb + cb * STAGEB;
#pragma unroll
        for (int ks = 0; ks < 4; ks++) {
            uint32_t kb = ks * 32 + bytesel;
            uint32_t ah[2][4];
#pragma unroll
            for (int mt = 0; mt < 2; mt++)
                ldsm4(ah[mt], s0 + O_AH + (wm0 + mt * 16 + rowoff) * ROWB + kb);
#pragma unroll
            for (int ng = 0; ng < 4; ng++) {
                uint32_t rb = (wn0 + ng * 16 + rowoff) * ROWB + kb;
                uint32_t bh[4];
                ldsm4(bh, s0 + O_BH + rb);
#pragma unroll
                for (int mt = 0; mt < 2; mt++) {
                    float* c0 = acc[mt][ng * 2];
                    float* c1 = acc[mt][ng * 2 + 1];
                    mma16816(c0, ah[mt], bh[0], bh[2]);
                    mma16816(c1, ah[mt], bh[1], bh[3]);
                }
            }
        }
        cb = (cb == 2) ? 0 : cb + 1;
        nb = (nb == 2) ? 0 : nb + 1;
    }

    // ---------------- epilogue ----------------
    if (G2) {
        int gcol = n0 + wn0 + (lane & 3) * 2;
#pragma unroll
        for (int mt = 0; mt < 2; mt++) {
#pragma unroll
            for (int half = 0; half < 2; half++) {
                int rloc = wm0 + mt * 16 + (lane >> 2) + half * 8;
                if (rloc >= mrem) continue;
                int gr = row0 + rloc;
                float wscale = g_wt[e * T_TOK + gr];
                int   tok    = g_list[e * T_TOK + gr];
                float* outp = out + (size_t)tok * HDIM + gcol;
#pragma unroll
                for (int nt = 0; nt < 8; nt++) {
                    atomicAdd(outp + nt * 8 + 0, acc[mt][nt][half * 2 + 0] * wscale);
                    atomicAdd(outp + nt * 8 + 1, acc[mt][nt][half * 2 + 1] * wscale);
                }
            }
        }
    } else {
        // interleaved cols: even=gate_i, odd=up_i ; pair index in I-space
        int pairBase = (n0 >> 1) + (wn0 >> 1) + (lane & 3);
#pragma unroll
        for (int mt = 0; mt < 2; mt++) {
#pragma unroll
            for (int half = 0; half < 2; half++) {
                int rloc = wm0 + mt * 16 + (lane >> 2) + half * 8;
                if (rloc >= mrem) continue;
                __half* dst = g_hh + (size_t)(base + row0 + rloc) * IDIM + pairBase;
#pragma unroll
                for (int nt = 0; nt < 8; nt++) {
                    float g = acc[mt][nt][half * 2 + 0];
                    float u = acc[mt][nt][half * 2 + 1];
                    float h = g / (1.f + expf(-g)) * u;
                    dst[nt * 4] = __float2half_rn(h);
                }
            }
        }
    }
}

// ---------------- launch --------------------------------------------------
extern "C" void kernel_launch(void* const* d_in, const int* in_sizes, int n_in,
                              void* d_out, int out_size) {
    const float* x  = (const float*)d_in[0];
    const float* rw = (const float*)d_in[1];
    const float* wg = (const float*)d_in[2];
    const float* wu = (const float*)d_in[3];
    const float* wd = (const float*)d_in[4];
    float* out = (float*)d_out;

    cudaFuncSetAttribute(k_gemm<HDIM, false>,
                         cudaFuncAttributeMaxDynamicSharedMemorySize, SMEM_TOTAL);
    cudaFuncSetAttribute(k_gemm<IDIM, true>,
                         cudaFuncAttributeMaxDynamicSharedMemorySize, SMEM_TOTAL);

    k_init<<<1, 32>>>();
    k_zero<<<(T_TOK * HDIM / 4 + 255) / 256, 256>>>(out);
    k_router<<<T_TOK / 8, 256>>>(x, rw);
    k_build<<<1, 1>>>();

    const size_t WG = (size_t)NEXP * IDIM * HDIM;
    const size_t WD = (size_t)NEXP * HDIM * IDIM;
    unsigned splitBlocks = (unsigned)(((2 * WG + WD) / 4 + 255) / 256);
    k_splitw<<<splitBlocks, 256>>>(wg, wu, wd);

    k_gather<<<NPAIR, 128>>>(x);

    dim3 g1(N2I / BN, MAXT);   // (22, 72)
    k_gemm<HDIM, false><<<g1, 256, SMEM_TOTAL>>>(nullptr);

    dim3 g2(HDIM / BN, MAXT);  // (8, 72)
    k_gemm<IDIM, true><<<g2, 256, SMEM_TOTAL>>>(out);
}